// round 12
// baseline (speedup 1.0000x reference)
#include <cuda_runtime.h>
#include <math_constants.h>

#define BS 32
#define NQ 256
#define NT 128
#define NC 2048
#define BT (BS * NT)                  // 4096
#define CSIZE ((size_t)BS * NQ * BT)  // 33554432
#define GRIDPAD 148                   // >=148 avoids low-grid issue throttle

#define SIGNBIT 0x8000000000000000ULL
#define KEYINF  0xFFFFFFFFFFFFFFFFULL

// signed int64 <-> unsigned sortable key (flip sign bit)
static __device__ __forceinline__ unsigned long long ikey(long long x) {
    return (unsigned long long)x ^ SIGNBIT;
}
static __device__ __forceinline__ long long unikey(unsigned long long k) {
    return (long long)(k ^ SIGNBIT);
}

// Pack f32 cost c = -prob into (mant<<5)|shift so that
// prob * 2^52 == (uint64)(pk >> 5) << (pk & 31), exactly.
// prob < 2^-29 (incl. zeros) -> pk = 0 (exact: those probs round to 0 cost
// only when exactly 0; for 2^-29..: e>=98 always true for normal softmax
// outputs of active rows; masked rows are exactly 0).
static __device__ __forceinline__ unsigned packcost(float c) {
    unsigned bb = __float_as_uint(c);
    unsigned mant = (bb & 0x7FFFFFu) | 0x800000u;
    int e = (int)((bb >> 23) & 0xFFu);
    return (e >= 98) ? ((mant << 5) | (unsigned)((e - 98) & 31)) : 0u;
}

// ---------------------------------------------------------------------------
// Kernel 1: masked softmax + gather into C = -prob   (~36us, memory-bound)
// ---------------------------------------------------------------------------
__global__ __launch_bounds__(256) void k_softmax_gather(
    const float* __restrict__ logits,
    const int*   __restrict__ tgt,
    const int*   __restrict__ mask,
    const int*   __restrict__ useBg,
    float*       __restrict__ out)
{
    __shared__ float sh[NC];
    __shared__ int   st[BT];
    __shared__ float red[8];

    const int row = blockIdx.x;
    const int tid = threadIdx.x;
    const int lane = tid & 31;
    const int warp = tid >> 5;

    const bool active = (useBg[0] != 0) || (mask[row] != 0);
    float* orow = out + (size_t)row * BT;

    if (!active) {
        const float4 z = make_float4(-0.0f, -0.0f, -0.0f, -0.0f);
        float4* o4 = (float4*)orow;
        #pragma unroll
        for (int j = tid; j < BT / 4; j += 256) o4[j] = z;
        return;
    }

    {
        const int4* tg4 = (const int4*)tgt;
        int4* st4 = (int4*)st;
        for (int j = tid; j < BT / 4; j += 256) st4[j] = tg4[j];
    }

    const float4* l4 = (const float4*)(logits + (size_t)row * NC);
    float4 v0 = l4[tid];
    float4 v1 = l4[tid + 256];

    float m = fmaxf(fmaxf(fmaxf(v0.x, v0.y), fmaxf(v0.z, v0.w)),
                    fmaxf(fmaxf(v1.x, v1.y), fmaxf(v1.z, v1.w)));
    #pragma unroll
    for (int o = 16; o; o >>= 1) m = fmaxf(m, __shfl_xor_sync(0xffffffffu, m, o));
    if (lane == 0) red[warp] = m;
    __syncthreads();
    if (tid == 0) {
        float t = red[0];
        #pragma unroll
        for (int w = 1; w < 8; w++) t = fmaxf(t, red[w]);
        red[0] = t;
    }
    __syncthreads();
    m = red[0];
    __syncthreads();

    float4 e0, e1;
    e0.x = expf(v0.x - m); e0.y = expf(v0.y - m);
    e0.z = expf(v0.z - m); e0.w = expf(v0.w - m);
    e1.x = expf(v1.x - m); e1.y = expf(v1.y - m);
    e1.z = expf(v1.z - m); e1.w = expf(v1.w - m);
    float s = (e0.x + e0.y) + (e0.z + e0.w) + (e1.x + e1.y) + (e1.z + e1.w);
    #pragma unroll
    for (int o = 16; o; o >>= 1) s += __shfl_xor_sync(0xffffffffu, s, o);
    if (lane == 0) red[warp] = s;
    __syncthreads();
    if (tid == 0) {
        float t = red[0];
        #pragma unroll
        for (int w = 1; w < 8; w++) t += red[w];
        red[0] = t;
    }
    __syncthreads();
    const float S = red[0];

    float4 p0, p1;
    p0.x = e0.x / S; p0.y = e0.y / S; p0.z = e0.z / S; p0.w = e0.w / S;
    p1.x = e1.x / S; p1.y = e1.y / S; p1.z = e1.z / S; p1.w = e1.w / S;
    ((float4*)sh)[tid]       = p0;
    ((float4*)sh)[tid + 256] = p1;
    __syncthreads();

    float4* o4 = (float4*)orow;
    const int4* st4 = (const int4*)st;
    #pragma unroll
    for (int j = tid; j < BT / 4; j += 256) {
        int4 id = st4[j];
        float4 o;
        o.x = -sh[id.x];
        o.y = -sh[id.y];
        o.z = -sh[id.z];
        o.w = -sh[id.w];
        o4[j] = o;
    }
}

// ---------------------------------------------------------------------------
// Kernel 2: Jonker-Volgenant, one block/batch, warp-0 solve; lane owns
// columns j = lane + 32k (k<8). EXACT int64 fixed-point (cost * 2^52):
// no rounding anywhere, so ordering matches scipy's f64 except for
// mathematically-equal values, which tie identically (lowest j) in both.
// R11 skeleton + pre-decoded packed costs + KEYINF-at-pop SC masking.
// ---------------------------------------------------------------------------
__global__ __launch_bounds__(256) void k_hungarian(
    const float* __restrict__ C,
    float* __restrict__ rows_out,
    float* __restrict__ cols_out)
{
    extern __shared__ unsigned cost[];    // [NT * NQ] packed (mant<<5)|shift
    __shared__ long long u[NT];
    __shared__ long long dsh[NQ];         // exact d at popped (SC) columns
    __shared__ int path[NQ];
    __shared__ int row4col[NQ];
    __shared__ int col4row[NT];

    const int b = blockIdx.x;
    if (b >= BS) return;                  // grid padded to dodge low-grid throttle
    const int tid = threadIdx.x;

    // load + transpose [NQ x NT] diagonal block into cost[t*NQ + q], packing
    // each f32 cost into (mant<<5)|shift (decode-free relax loop).
    {
        const float4* src = (const float4*)(C + ((size_t)(b * NQ + tid)) * BT + b * NT);
        #pragma unroll
        for (int t4 = 0; t4 < NT / 4; t4++) {
            float4 vv = src[t4];
            int t = t4 * 4;
            cost[(t + 0) * NQ + tid] = packcost(vv.x);
            cost[(t + 1) * NQ + tid] = packcost(vv.y);
            cost[(t + 2) * NQ + tid] = packcost(vv.z);
            cost[(t + 3) * NQ + tid] = packcost(vv.w);
        }
    }
    if (tid < NT) { u[tid] = 0ll; col4row[tid] = -1; }
    row4col[tid] = -1;
    __syncthreads();

    if (tid >= 32) return;   // warp 0 only
    const int lane = tid;
    const unsigned FULL = 0xffffffffu;

    long long vfix[8];
    #pragma unroll
    for (int k = 0; k < 8; k++) vfix[k] = 0ll;

    for (int cur = 0; cur < NT; cur++) {
        unsigned long long dk[8];   // d as unsigned sortable keys; KEYINF once popped
        long long pv[8];            // pop-time d value (for exact v update)
        #pragma unroll
        for (int k = 0; k < 8; k++) dk[k] = KEYINF;
        unsigned sc = 0;        // SC bits for lane's 8 columns
        unsigned srbits = 0;    // SR bits for lane's 4 rows (row = lane + 32k)
        long long minFix = 0ll;
        int i = cur;
        long long ufi = u[cur];
        int sink;

        #pragma unroll 1
        for (;;) {
            // SR[i] = 1 (register-resident; branchless)
            srbits |= (unsigned)((i & 31) == lane) << (i >> 5);

            // relax row i: r = minVal + cost - u[i] - v[j], exact int64
            const long long base = minFix - ufi;
            const unsigned* crow = cost + i * NQ;
            unsigned c[8];
            #pragma unroll
            for (int k = 0; k < 8; k++) c[k] = crow[lane + 32 * k];
            #pragma unroll
            for (int k = 0; k < 8; k++) {
                const long long val = (long long)(c[k] >> 5) << (c[k] & 31u);
                const long long r = (base - vfix[k]) - val;   // cost = -val
                const unsigned long long rk = ikey(r);
                const bool upd = (rk < dk[k]) & !((sc >> k) & 1u);
                if (upd) {
                    dk[k] = rk;
                    path[lane + 32 * k] = i;
                }
            }

            // lane-local argmin directly on dk (SC slots are KEYINF)
            unsigned long long K[8]; int J[8];
            #pragma unroll
            for (int k = 0; k < 8; k++) { K[k] = dk[k]; J[k] = lane + 32 * k; }
            #pragma unroll
            for (int s = 1; s < 8; s <<= 1) {
                #pragma unroll
                for (int k = 0; k < 8; k += 2 * s) {
                    if (K[k + s] < K[k]) { K[k] = K[k + s]; J[k] = J[k + s]; }
                }
            }

            // warp argmin: straight-line 3x REDUX
            unsigned hi = (unsigned)(K[0] >> 32);
            unsigned lo = (unsigned)K[0];
            unsigned mhi = __reduce_min_sync(FULL, hi);
            unsigned lo2 = (hi == mhi) ? lo : 0xFFFFFFFFu;
            unsigned mlo = __reduce_min_sync(FULL, lo2);
            unsigned jc  = (hi == mhi && lo == mlo) ? (unsigned)J[0] : 0xFFFFFFFFu;
            const int bestj = (int)__reduce_min_sync(FULL, jc);

            minFix = unikey(((unsigned long long)mhi << 32) | mlo);

            // pop bookkeeping, branchless / predicated
            const bool owner = ((bestj & 31) == lane);
            const int kk = bestj >> 5;
            sc |= (unsigned)owner << kk;
            if (owner) {
                dsh[bestj] = minFix;          // for u updates (arbitrary cols)
                pv[kk] = minFix;              // for this lane's v update
                dk[kk] = KEYINF;              // drop from future argmins
            }

            const int rj = row4col[bestj];
            if (rj < 0) { sink = bestj; break; }
            i = rj;
            ufi = u[rj];
        }
        __syncwarp();

        // dual updates (exact int64); row-owner lanes update u
        #pragma unroll
        for (int k = 0; k < 4; k++) {
            if ((srbits >> k) & 1u) {
                const int r = lane + 32 * k;
                if (r == cur) {
                    u[r] = u[r] + minFix;
                } else {
                    const int j = col4row[r];
                    u[r] = u[r] + (minFix - dsh[j]);
                }
            }
        }
        #pragma unroll
        for (int k = 0; k < 8; k++) {
            if ((sc >> k) & 1u)
                vfix[k] = vfix[k] - (minFix - pv[k]);
        }
        __syncwarp();

        // augment along shortest path (lane 0 serial)
        if (lane == 0) {
            int j = sink;
            while (true) {
                const int ii = path[j];
                row4col[j] = ii;
                const int jn = col4row[ii];
                col4row[ii] = j;
                j = jn;
                if (ii == cur) break;
            }
        }
        __syncwarp();
    }

    // emit: rows = sorted assigned queries, cols = corresponding targets
    #pragma unroll
    for (int k = 0; k < 4; k++) {
        const int t = lane + 32 * k;
        const int q = col4row[t];
        int rank = 0;
        for (int t2 = 0; t2 < NT; t2++) rank += (col4row[t2] < q) ? 1 : 0;
        rows_out[b * NT + rank] = (float)q;
        cols_out[b * NT + rank] = (float)t;
    }
}

// ---------------------------------------------------------------------------
extern "C" void kernel_launch(void* const* d_in, const int* in_sizes, int n_in,
                              void* d_out, int out_size)
{
    const float* logits = (const float*)d_in[0];   // [32,256,2048] f32
    const int*   tgt    = (const int*)d_in[1];     // [32,128] i32
    const int*   mask   = (const int*)d_in[2];     // [32,256] i32
    const int*   useBg  = (const int*)d_in[3];     // [1] i32

    float* out  = (float*)d_out;
    float* rows = out + CSIZE;
    float* cols = rows + (size_t)BS * NT;

    k_softmax_gather<<<BS * NQ, 256>>>(logits, tgt, mask, useBg, out);

    cudaFuncSetAttribute(k_hungarian, cudaFuncAttributeMaxDynamicSharedMemorySize,
                         NT * NQ * (int)sizeof(unsigned));
    k_hungarian<<<GRIDPAD, 256, NT * NQ * sizeof(unsigned)>>>(out, rows, cols);
}

// round 15
// speedup vs baseline: 1.4933x; 1.4933x over previous
#include <cuda_runtime.h>
#include <math_constants.h>

#define BS 32
#define NQ 256
#define NT 128
#define NC 2048
#define BT (BS * NT)                  // 4096
#define CSIZE ((size_t)BS * NQ * BT)  // 33554432
#define GRIDPAD 148                   // >=148 avoids low-grid issue throttle

#define SIGNBIT 0x8000000000000000ULL
#define KEYINF  0xFFFFFFFFFFFFFFFFULL

// signed int64 <-> unsigned sortable key (flip sign bit)
static __device__ __forceinline__ unsigned long long ikey(long long x) {
    return (unsigned long long)x ^ SIGNBIT;
}
static __device__ __forceinline__ long long unikey(unsigned long long k) {
    return (long long)(k ^ SIGNBIT);
}

// Pack f32 cost c = -prob into (mant<<5)|shift so that
// prob * 2^52 == (uint64)(pk >> 5) << (pk & 31), exactly.
// e < 98 (prob < 2^-29, incl. exact zeros from masking) -> pk = 0.
static __device__ __forceinline__ unsigned packcost(float c) {
    unsigned bb = __float_as_uint(c);
    unsigned mant = (bb & 0x7FFFFFu) | 0x800000u;
    int e = (int)((bb >> 23) & 0xFFu);
    return (e >= 98) ? ((mant << 5) | (unsigned)((e - 98) & 31)) : 0u;
}

// ---------------------------------------------------------------------------
// Kernel 1: masked softmax + gather into C = -prob   (~36us, memory-bound)
// ---------------------------------------------------------------------------
__global__ __launch_bounds__(256) void k_softmax_gather(
    const float* __restrict__ logits,
    const int*   __restrict__ tgt,
    const int*   __restrict__ mask,
    const int*   __restrict__ useBg,
    float*       __restrict__ out)
{
    __shared__ float sh[NC];
    __shared__ int   st[BT];
    __shared__ float red[8];

    const int row = blockIdx.x;
    const int tid = threadIdx.x;
    const int lane = tid & 31;
    const int warp = tid >> 5;

    const bool active = (useBg[0] != 0) || (mask[row] != 0);
    float* orow = out + (size_t)row * BT;

    if (!active) {
        const float4 z = make_float4(-0.0f, -0.0f, -0.0f, -0.0f);
        float4* o4 = (float4*)orow;
        #pragma unroll
        for (int j = tid; j < BT / 4; j += 256) o4[j] = z;
        return;
    }

    {
        const int4* tg4 = (const int4*)tgt;
        int4* st4 = (int4*)st;
        for (int j = tid; j < BT / 4; j += 256) st4[j] = tg4[j];
    }

    const float4* l4 = (const float4*)(logits + (size_t)row * NC);
    float4 v0 = l4[tid];
    float4 v1 = l4[tid + 256];

    float m = fmaxf(fmaxf(fmaxf(v0.x, v0.y), fmaxf(v0.z, v0.w)),
                    fmaxf(fmaxf(v1.x, v1.y), fmaxf(v1.z, v1.w)));
    #pragma unroll
    for (int o = 16; o; o >>= 1) m = fmaxf(m, __shfl_xor_sync(0xffffffffu, m, o));
    if (lane == 0) red[warp] = m;
    __syncthreads();
    if (tid == 0) {
        float t = red[0];
        #pragma unroll
        for (int w = 1; w < 8; w++) t = fmaxf(t, red[w]);
        red[0] = t;
    }
    __syncthreads();
    m = red[0];
    __syncthreads();

    float4 e0, e1;
    e0.x = expf(v0.x - m); e0.y = expf(v0.y - m);
    e0.z = expf(v0.z - m); e0.w = expf(v0.w - m);
    e1.x = expf(v1.x - m); e1.y = expf(v1.y - m);
    e1.z = expf(v1.z - m); e1.w = expf(v1.w - m);
    float s = (e0.x + e0.y) + (e0.z + e0.w) + (e1.x + e1.y) + (e1.z + e1.w);
    #pragma unroll
    for (int o = 16; o; o >>= 1) s += __shfl_xor_sync(0xffffffffu, s, o);
    if (lane == 0) red[warp] = s;
    __syncthreads();
    if (tid == 0) {
        float t = red[0];
        #pragma unroll
        for (int w = 1; w < 8; w++) t += red[w];
        red[0] = t;
    }
    __syncthreads();
    const float S = red[0];

    float4 p0, p1;
    p0.x = e0.x / S; p0.y = e0.y / S; p0.z = e0.z / S; p0.w = e0.w / S;
    p1.x = e1.x / S; p1.y = e1.y / S; p1.z = e1.z / S; p1.w = e1.w / S;
    ((float4*)sh)[tid]       = p0;
    ((float4*)sh)[tid + 256] = p1;
    __syncthreads();

    float4* o4 = (float4*)orow;
    const int4* st4 = (const int4*)st;
    #pragma unroll
    for (int j = tid; j < BT / 4; j += 256) {
        int4 id = st4[j];
        float4 o;
        o.x = -sh[id.x];
        o.y = -sh[id.y];
        o.z = -sh[id.z];
        o.w = -sh[id.w];
        o4[j] = o;
    }
}

// ---------------------------------------------------------------------------
// Kernel 2: Jonker-Volgenant, one block/batch, warp-0 solve; lane owns
// columns j = lane + 32k (k<8). EXACT int64 fixed-point (cost * 2^52):
// no rounding anywhere, so ordering matches scipy's f64 except for
// mathematically-equal values, which tie identically (lowest j) in both.
// R11 skeleton (all register arrays statically indexed) with pre-packed
// costs in shared memory: relax decode = SHR + SHF64.
// ---------------------------------------------------------------------------
__global__ __launch_bounds__(256) void k_hungarian(
    const float* __restrict__ C,
    float* __restrict__ rows_out,
    float* __restrict__ cols_out)
{
    extern __shared__ unsigned cost[];    // [NT * NQ] packed (mant<<5)|shift
    __shared__ long long u[NT];
    __shared__ long long dsh[NQ];         // exact d at popped (SC) columns
    __shared__ int path[NQ];
    __shared__ int row4col[NQ];
    __shared__ int col4row[NT];

    const int b = blockIdx.x;
    if (b >= BS) return;                  // grid padded to dodge low-grid throttle
    const int tid = threadIdx.x;

    // load + transpose [NQ x NT] diagonal block into cost[t*NQ + q], packing
    // each f32 cost into (mant<<5)|shift during the (memory-bound) load.
    {
        const float4* src = (const float4*)(C + ((size_t)(b * NQ + tid)) * BT + b * NT);
        #pragma unroll
        for (int t4 = 0; t4 < NT / 4; t4++) {
            float4 vv = src[t4];
            int t = t4 * 4;
            cost[(t + 0) * NQ + tid] = packcost(vv.x);
            cost[(t + 1) * NQ + tid] = packcost(vv.y);
            cost[(t + 2) * NQ + tid] = packcost(vv.z);
            cost[(t + 3) * NQ + tid] = packcost(vv.w);
        }
    }
    if (tid < NT) { u[tid] = 0ll; col4row[tid] = -1; }
    row4col[tid] = -1;
    __syncthreads();

    if (tid >= 32) return;   // warp 0 only
    const int lane = tid;
    const unsigned FULL = 0xffffffffu;

    long long vfix[8];
    #pragma unroll
    for (int k = 0; k < 8; k++) vfix[k] = 0ll;

    for (int cur = 0; cur < NT; cur++) {
        unsigned long long dk[8];   // d as unsigned sortable keys
        #pragma unroll
        for (int k = 0; k < 8; k++) dk[k] = KEYINF;
        unsigned sc = 0;        // SC bits for lane's 8 columns
        unsigned srbits = 0;    // SR bits for lane's 4 rows (row = lane + 32k)
        long long minFix = 0ll;
        int i = cur;
        long long ufi = u[cur];
        int sink;

        #pragma unroll 1
        for (;;) {
            // SR[i] = 1 (register-resident; branchless)
            srbits |= (unsigned)((i & 31) == lane) << (i >> 5);

            // relax row i: r = minVal + cost - u[i] - v[j], exact int64
            const long long base = minFix - ufi;
            const unsigned* crow = cost + i * NQ;
            unsigned c[8];
            #pragma unroll
            for (int k = 0; k < 8; k++) c[k] = crow[lane + 32 * k];
            #pragma unroll
            for (int k = 0; k < 8; k++) {
                const long long val = (long long)(c[k] >> 5) << (c[k] & 31u);
                const long long r = (base - vfix[k]) - val;   // cost = -val
                const unsigned long long rk = ikey(r);
                const bool upd = (rk < dk[k]) & !((sc >> k) & 1u);
                if (upd) {
                    dk[k] = rk;
                    path[lane + 32 * k] = i;
                }
            }

            // lane-local argmin (ties -> lowest j == lowest k); SC masked
            unsigned long long K[8]; int J[8];
            #pragma unroll
            for (int k = 0; k < 8; k++) {
                K[k] = ((sc >> k) & 1u) ? KEYINF : dk[k];
                J[k] = lane + 32 * k;
            }
            #pragma unroll
            for (int s = 1; s < 8; s <<= 1) {
                #pragma unroll
                for (int k = 0; k < 8; k += 2 * s) {
                    if (K[k + s] < K[k]) { K[k] = K[k + s]; J[k] = J[k + s]; }
                }
            }

            // warp argmin: straight-line 3x REDUX (no divergent fast path)
            unsigned hi = (unsigned)(K[0] >> 32);
            unsigned lo = (unsigned)K[0];
            unsigned mhi = __reduce_min_sync(FULL, hi);
            unsigned lo2 = (hi == mhi) ? lo : 0xFFFFFFFFu;
            unsigned mlo = __reduce_min_sync(FULL, lo2);
            unsigned jc  = (hi == mhi && lo == mlo) ? (unsigned)J[0] : 0xFFFFFFFFu;
            const int bestj = (int)__reduce_min_sync(FULL, jc);

            minFix = unikey(((unsigned long long)mhi << 32) | mlo);

            // pop bookkeeping, branchless / predicated
            const bool owner = ((bestj & 31) == lane);
            sc |= (unsigned)owner << (bestj >> 5);
            if (owner) dsh[bestj] = minFix;     // single predicated STS

            const int rj = row4col[bestj];
            if (rj < 0) { sink = bestj; break; }
            i = rj;
            ufi = u[rj];
        }
        __syncwarp();

        // dual updates (exact int64); row-owner lanes update u
        #pragma unroll
        for (int k = 0; k < 4; k++) {
            if ((srbits >> k) & 1u) {
                const int r = lane + 32 * k;
                if (r == cur) {
                    u[r] = u[r] + minFix;
                } else {
                    const int j = col4row[r];
                    u[r] = u[r] + (minFix - dsh[j]);
                }
            }
        }
        #pragma unroll
        for (int k = 0; k < 8; k++) {
            if ((sc >> k) & 1u)
                vfix[k] = vfix[k] - (minFix - unikey(dk[k]));
        }
        __syncwarp();

        // augment along shortest path (lane 0 serial)
        if (lane == 0) {
            int j = sink;
            while (true) {
                const int ii = path[j];
                row4col[j] = ii;
                const int jn = col4row[ii];
                col4row[ii] = j;
                j = jn;
                if (ii == cur) break;
            }
        }
        __syncwarp();
    }

    // emit: rows = sorted assigned queries, cols = corresponding targets
    #pragma unroll
    for (int k = 0; k < 4; k++) {
        const int t = lane + 32 * k;
        const int q = col4row[t];
        int rank = 0;
        for (int t2 = 0; t2 < NT; t2++) rank += (col4row[t2] < q) ? 1 : 0;
        rows_out[b * NT + rank] = (float)q;
        cols_out[b * NT + rank] = (float)t;
    }
}

// ---------------------------------------------------------------------------
extern "C" void kernel_launch(void* const* d_in, const int* in_sizes, int n_in,
                              void* d_out, int out_size)
{
    const float* logits = (const float*)d_in[0];   // [32,256,2048] f32
    const int*   tgt    = (const int*)d_in[1];     // [32,128] i32
    const int*   mask   = (const int*)d_in[2];     // [32,256] i32
    const int*   useBg  = (const int*)d_in[3];     // [1] i32

    float* out  = (float*)d_out;
    float* rows = out + CSIZE;
    float* cols = rows + (size_t)BS * NT;

    k_softmax_gather<<<BS * NQ, 256>>>(logits, tgt, mask, useBg, out);

    cudaFuncSetAttribute(k_hungarian, cudaFuncAttributeMaxDynamicSharedMemorySize,
                         NT * NQ * (int)sizeof(unsigned));
    k_hungarian<<<GRIDPAD, 256, NT * NQ * sizeof(unsigned)>>>(out, rows, cols);
}